// round 2
// baseline (speedup 1.0000x reference)
#include <cuda_runtime.h>
#include <math.h>
#include <stdint.h>

// ---------------- problem constants ----------------
#define BQ 16
#define NQ 2048
#define DQ 64
#define SQ 512          // NPOINT
#define NSQ 32          // NSAMPLE
#define SCQ 67          // D+3
#define INCH 134        // 2*D+6
#define C0Q 128
#define C1Q 128
#define C2Q 256
#define KSQ (NSQ*SQ)    // 16384
#define JQ (3+DQ+NSQ*DQ+NSQ*3)  // 2211
#define OFF_X 0
#define OFF_P 3
#define OFF_GP 67
#define OFF_GX 2115
#define XYZ_OUT (BQ*3*SQ)            // 24576
#define NP_OUT  ((size_t)BQ*C2Q*SQ)  // 2097152

// ---------------- scratch (device globals; no allocations) ----------------
__device__ float g_agg[(size_t)BQ*SCQ*NQ];
__device__ float g_h1 [(size_t)BQ*SCQ*NQ];
__device__ float g_h2 [(size_t)BQ*SQ*NQ];      // becomes `select` in place
__device__ float g_selT[(size_t)BQ*NQ*SQ];
__device__ float g_inner[(size_t)BQ*SQ*SQ];
__device__ float g_norm[BQ*SQ];
__device__ int   g_amax[SQ];
__device__ int   g_idx[(size_t)BQ*NQ*NSQ];
__device__ float g_ptst[(size_t)BQ*NQ*DQ];
__device__ float g_xyzt[(size_t)BQ*NQ*3];
__device__ float g_Bmat[(size_t)BQ*NQ*JQ];
__device__ float g_Cbig[(size_t)BQ*SQ*JQ];
__device__ float g_E  [(size_t)BQ*INCH*KSQ];
__device__ float g_O0 [(size_t)BQ*C0Q*KSQ];
__device__ float g_O1 [(size_t)BQ*C1Q*KSQ];
__device__ float g_O2 [(size_t)BQ*C2Q*KSQ];
__device__ float g_s1[SCQ],  g_sh1[SCQ];
__device__ float g_s2[SQ],   g_sh2[SQ];
__device__ float g_sc0[C0Q], g_sf0[C0Q];
__device__ float g_sc1[C1Q], g_sf1[C1Q];
__device__ float g_sc2[C2Q], g_sf2[C2Q];
__device__ float g_acc[BQ];
__device__ int   g_flags[NQ];

// ---------------- generic SGEMM: C[b] = A[b](MxK) * B[b](KxN) (+bias, B-affine+leaky) ----
__global__ void __launch_bounds__(256) sa_gemm(
    const float* __restrict__ A, const float* __restrict__ Bm, float* __restrict__ C,
    int M, int Ncol, int K,
    size_t sAb, size_t sBb, size_t sCb,
    const float* __restrict__ bias,
    const float* __restrict__ bsc, const float* __restrict__ bsh)
{
    __shared__ float As[8][128];
    __shared__ float Bs[8][128];
    const int b = blockIdx.z;
    const float* Ab = A + (size_t)b * sAb;
    const float* Bb = Bm + (size_t)b * sBb;
    float* Cb = C + (size_t)b * sCb;
    const int tid = threadIdx.x;
    const int row0 = blockIdx.y * 128;
    const int col0 = blockIdx.x * 128;
    const int ra = (tid >> 4) * 4;
    const int ca = (tid & 15) * 4;
    float acc[8][8];
#pragma unroll
    for (int i = 0; i < 8; i++)
#pragma unroll
        for (int j = 0; j < 8; j++) acc[i][j] = 0.f;

    const int la_m = tid >> 1;
    const int la_k = (tid & 1) * 4;
    const int lb_k = tid >> 5;
    const int lb_n = (tid & 31) * 4;

    for (int k0 = 0; k0 < K; k0 += 8) {
        {
            int arow = row0 + la_m;
#pragma unroll
            for (int u = 0; u < 4; u++) {
                int kk = k0 + la_k + u;
                float v = (arow < M && kk < K) ? Ab[(size_t)arow * K + kk] : 0.f;
                As[la_k + u][la_m] = v;
            }
        }
        {
            int krow = k0 + lb_k;
            bool kv = krow < K;
            float sc = 1.f, sh = 0.f;
            if (bsc && kv) { sc = bsc[krow]; sh = bsh[krow]; }
#pragma unroll
            for (int u = 0; u < 4; u++) {
                int col = col0 + lb_n + u;
                float v = 0.f;
                if (kv && col < Ncol) {
                    v = Bb[(size_t)krow * Ncol + col];
                    if (bsc) { float y = sc * v + sh; v = (y >= 0.f) ? y : 0.2f * y; }
                }
                Bs[lb_k][lb_n + u] = v;
            }
        }
        __syncthreads();
#pragma unroll
        for (int kk = 0; kk < 8; kk++) {
            float4 a0 = *(const float4*)&As[kk][ra];
            float4 a1 = *(const float4*)&As[kk][64 + ra];
            float4 b0 = *(const float4*)&Bs[kk][ca];
            float4 b1 = *(const float4*)&Bs[kk][64 + ca];
            float av[8] = {a0.x,a0.y,a0.z,a0.w,a1.x,a1.y,a1.z,a1.w};
            float bv[8] = {b0.x,b0.y,b0.z,b0.w,b1.x,b1.y,b1.z,b1.w};
#pragma unroll
            for (int i = 0; i < 8; i++)
#pragma unroll
                for (int j = 0; j < 8; j++)
                    acc[i][j] += av[i] * bv[j];
        }
        __syncthreads();
    }
#pragma unroll
    for (int i = 0; i < 8; i++) {
        int r = row0 + ((i < 4) ? (ra + i) : (64 + ra + i - 4));
        if (r >= M) continue;
        float bi = bias ? bias[r] : 0.f;
#pragma unroll
        for (int j = 0; j < 8; j++) {
            int c = col0 + ((j < 4) ? (ca + j) : (64 + ca + j - 4));
            if (c < Ncol) Cb[(size_t)r * Ncol + c] = acc[i][j] + bi;
        }
    }
}

// ---------------- small helpers ----------------
__global__ void sa_init() {
    int i = blockIdx.x * 256 + threadIdx.x;
    if (i < NQ) g_flags[i] = 0;
    if (i < BQ) g_acc[i] = 0.f;
}

__global__ void sa_agg(const float* __restrict__ points, const float* __restrict__ xyz) {
    size_t i = (size_t)blockIdx.x * 256 + threadIdx.x;
    if (i >= (size_t)BQ*SCQ*NQ) return;
    int n = (int)(i % NQ); size_t r = i / NQ; int c = (int)(r % SCQ); int b = (int)(r / SCQ);
    float v = (c < DQ) ? points[((size_t)b*DQ + c)*NQ + n]
                       : xyz[((size_t)b*3 + (c - DQ))*NQ + n];
    g_agg[i] = v;
}

// (B,C,N) -> (B,N,C)
__global__ void sa_tr(const float* __restrict__ src, float* __restrict__ dst, int C) {
    size_t i = (size_t)blockIdx.x * 256 + threadIdx.x;
    if (i >= (size_t)BQ * NQ * C) return;
    int c = (int)(i % C); size_t r = i / C; int n = (int)(r % NQ); int b = (int)(r / NQ);
    dst[i] = src[((size_t)b * C + c) * NQ + n];
}

// ball query: warp per (b,n), ordered first-32 under radius
__global__ void sa_ball(const float* __restrict__ xyz) {
    int w = (blockIdx.x * blockDim.x + threadIdx.x) >> 5;
    int lane = threadIdx.x & 31;
    if (w >= BQ * NQ) return;
    int b = w / NQ, n = w % NQ;
    const float* X = xyz + (size_t)b * 3 * NQ;
    float px = X[n], py = X[NQ + n], pz = X[2 * NQ + n];
    float pn = px*px + py*py + pz*pz;
    const float RR = (float)(0.2 * 0.2);
    int* out = g_idx + ((size_t)b * NQ + n) * NSQ;
    int cnt = 0;
    for (int j0 = 0; j0 < NQ && cnt < NSQ; j0 += 32) {
        int j = j0 + lane;
        float qx = X[j], qy = X[NQ + j], qz = X[2 * NQ + j];
        float qn = qx*qx + qy*qy + qz*qz;
        float sq = (pn + qn) - 2.0f * (px*qx + py*qy + pz*qz);
        bool in = !(sq > RR);
        unsigned m = __ballot_sync(0xffffffffu, in);
        int pos = cnt + __popc(m & ((1u << lane) - 1u));
        if (in && pos < NSQ) out[pos] = j;
        cnt += __popc(m);
    }
    __syncwarp();
    if (lane == 0) {
        int first = out[0];
        for (int t = cnt; t < NSQ; t++) out[t] = first;
    }
}

// per-channel BN stats over (B, L): scale/shift
__global__ void sa_stats(const float* __restrict__ X, int Cch, int L,
                         const float* __restrict__ gamma, const float* __restrict__ beta,
                         float* __restrict__ sc, float* __restrict__ sf)
{
    int c = blockIdx.x;
    int tid = threadIdx.x;
    double s = 0.0, s2 = 0.0;
    for (int b = 0; b < BQ; b++) {
        const float* p = X + ((size_t)b * Cch + c) * L;
        for (int i = tid; i < L; i += 256) { double v = p[i]; s += v; s2 += v * v; }
    }
    __shared__ double ss[256], ss2[256];
    ss[tid] = s; ss2[tid] = s2; __syncthreads();
    for (int o = 128; o > 0; o >>= 1) {
        if (tid < o) { ss[tid] += ss[tid + o]; ss2[tid] += ss2[tid + o]; }
        __syncthreads();
    }
    if (tid == 0) {
        double n = (double)BQ * L;
        double m = ss[0] / n;
        double var = ss2[0] / n - m * m;
        if (var < 0.0) var = 0.0;
        float scale = gamma[c] * rsqrtf((float)var + 1e-5f);
        sc[c] = scale;
        sf[c] = beta[c] - (float)m * scale;
    }
}

__global__ void sa_bnapply(float* __restrict__ X, const float* __restrict__ sc,
                           const float* __restrict__ sf, int Cch, int L) {
    size_t i = (size_t)blockIdx.x * 256 + threadIdx.x;
    if (i >= (size_t)BQ * Cch * L) return;
    int c = (int)((i / L) % Cch);
    X[i] = sc[c] * X[i] + sf[c];
}

// softmax over N per (b,s) row, in place; also norm + argmax(b==0)
__global__ void sa_softmax(float* __restrict__ H) {
    int s = blockIdx.x, b = blockIdx.y;
    float* row = H + ((size_t)b * SQ + s) * NQ;
    __shared__ float buf[NQ];
    __shared__ float red[256];
    __shared__ float rv[256];
    __shared__ int   ri[256];
    int tid = threadIdx.x;
    float a = g_s2[s], sh = g_sh2[s];
    float lmax = -3.4e38f;
    for (int i = tid; i < NQ; i += 256) {
        float y = a * row[i] + sh;
        buf[i] = y;
        lmax = fmaxf(lmax, y);
    }
    red[tid] = lmax; __syncthreads();
    for (int o = 128; o > 0; o >>= 1) { if (tid < o) red[tid] = fmaxf(red[tid], red[tid + o]); __syncthreads(); }
    float gmax = red[0]; __syncthreads();
    float lsum = 0.f;
    for (int i = tid; i < NQ; i += 256) { float e = expf(buf[i] - gmax); buf[i] = e; lsum += e; }
    red[tid] = lsum; __syncthreads();
    for (int o = 128; o > 0; o >>= 1) { if (tid < o) red[tid] += red[tid + o]; __syncthreads(); }
    float inv = 1.f / red[0]; __syncthreads();
    float lss = 0.f, bm = -1.f; int bi = 0;
    for (int i = tid; i < NQ; i += 256) {
        float v = buf[i] * inv;
        row[i] = v;
        lss += v * v;
        if (v > bm) { bm = v; bi = i; }
    }
    red[tid] = lss; rv[tid] = bm; ri[tid] = bi; __syncthreads();
    for (int o = 128; o > 0; o >>= 1) {
        if (tid < o) {
            red[tid] += red[tid + o];
            if (rv[tid + o] > rv[tid] || (rv[tid + o] == rv[tid] && ri[tid + o] < ri[tid])) {
                rv[tid] = rv[tid + o]; ri[tid] = ri[tid + o];
            }
        }
        __syncthreads();
    }
    if (tid == 0) {
        g_norm[b * SQ + s] = sqrtf(red[0]);
        if (b == 0) g_amax[s] = ri[0];
    }
}

__global__ void sa_flags() {
    int s = blockIdx.x * 256 + threadIdx.x;
    if (s < SQ) g_flags[g_amax[s]] = 1;
}

// select (b,s,n) -> selT (b,n,s)
__global__ void sa_selT() {
    __shared__ float t[32][33];
    int b = blockIdx.z;
    int n0 = blockIdx.x * 32, s0 = blockIdx.y * 32;
    const float* Sb = g_h2 + (size_t)b * SQ * NQ;
    float* Tb = g_selT + (size_t)b * NQ * SQ;
    int x = threadIdx.x, y = threadIdx.y;
    for (int yy = y; yy < 32; yy += 8)
        t[yy][x] = Sb[(size_t)(s0 + yy) * NQ + (n0 + x)];
    __syncthreads();
    for (int yy = y; yy < 32; yy += 8)
        Tb[(size_t)(n0 + yy) * SQ + (s0 + x)] = t[x][yy];
}

__global__ void sa_cos_epi() {
    size_t i = (size_t)blockIdx.x * 256 + threadIdx.x;
    int b = (int)(i / ((size_t)SQ * SQ));
    int r = (int)((i / SQ) % SQ);
    int c = (int)(i % SQ);
    float v = 0.f;
    if (r != c) {
        float in = g_inner[i];
        float d = g_norm[b * SQ + r] * g_norm[b * SQ + c] + 1e-10f;
        float cm = in / d;
        v = cm * cm;
    }
    __shared__ float red[256];
    red[threadIdx.x] = v; __syncthreads();
    for (int o = 128; o > 0; o >>= 1) { if (threadIdx.x < o) red[threadIdx.x] += red[threadIdx.x + o]; __syncthreads(); }
    if (threadIdx.x == 0) atomicAdd(&g_acc[b], red[0]);
}

// build (n x 2211) gather matrix per (b,n)
__global__ void sa_bmat() {
    int n = blockIdx.x, b = blockIdx.y;
    float* row = g_Bmat + ((size_t)b * NQ + n) * JQ;
    const float* xt = g_xyzt + (size_t)b * NQ * 3;
    const float* pt = g_ptst + (size_t)b * NQ * DQ;
    __shared__ int sidx[NSQ];
    int tid = threadIdx.x;
    if (tid < NSQ) sidx[tid] = g_idx[((size_t)b * NQ + n) * NSQ + tid];
    __syncthreads();
    if (tid < 3) row[OFF_X + tid] = xt[(size_t)n * 3 + tid];
    for (int d = tid; d < DQ; d += 256) row[OFF_P + d] = pt[(size_t)n * DQ + d];
    for (int t = tid; t < NSQ * DQ; t += 256) {
        int k = t / DQ, d = t % DQ;
        row[OFF_GP + t] = pt[(size_t)sidx[k] * DQ + d];
    }
    for (int t = tid; t < NSQ * 3; t += 256) {
        int k = t / 3, c = t % 3;
        row[OFF_GX + t] = xt[(size_t)sidx[k] * 3 + c];
    }
}

__global__ void sa_newxyz(float* __restrict__ out) {
    int i = blockIdx.x * 256 + threadIdx.x;
    if (i >= BQ * 3 * SQ) return;
    int s = i % SQ; int c = (i / SQ) % 3; int b = i / (3 * SQ);
    out[i] = g_Cbig[((size_t)b * SQ + s) * JQ + c];
}

__global__ void sa_edge() {
    size_t i = (size_t)blockIdx.x * 256 + threadIdx.x;
    if (i >= (size_t)BQ * INCH * KSQ) return;
    int s = (int)(i % SQ); size_t r = i / SQ;
    int k = (int)(r % NSQ); r /= NSQ;
    int ch = (int)(r % INCH); int b = (int)(r / INCH);
    const float* Crow = g_Cbig + ((size_t)b * SQ + s) * JQ;
    float v;
    if (ch < 64) v = Crow[OFF_P + ch];
    else if (ch < 128) { int d = ch - 64; v = Crow[OFF_GP + k * DQ + d] - Crow[OFF_P + d]; }
    else if (ch < 131) v = Crow[OFF_X + (ch - 128)];
    else { int c3 = ch - 131; v = Crow[OFF_GX + k * 3 + c3] - Crow[OFF_X + c3]; }
    g_E[i] = v;
}

__global__ void sa_max(float* __restrict__ out) {
    size_t i = (size_t)blockIdx.x * 256 + threadIdx.x;
    if (i >= NP_OUT) return;
    int s = (int)(i % SQ); int o = (int)((i / SQ) % C2Q); int b = (int)(i / ((size_t)SQ * C2Q));
    float sc = g_sc2[o], sf = g_sf2[o];
    const float* p = g_O2 + ((size_t)b * C2Q + o) * KSQ + s;
    float m = -3.4e38f;
#pragma unroll
    for (int k = 0; k < NSQ; k++) {
        float x = p[(size_t)k * SQ];
        float y = sc * x + sf;
        y = (y >= 0.f) ? y : 0.2f * y;
        m = fmaxf(m, y);
    }
    out[XYZ_OUT + i] = m;
}

__global__ void sa_scalars(float* __restrict__ out) {
    __shared__ float sfr[256];
    __shared__ int sir[256];
    int tid = threadIdx.x;
    int cnt = 0;
    for (int i = tid; i < NQ; i += 256) cnt += g_flags[i];
    float l = (tid < BQ) ? sqrtf(g_acc[tid]) : 0.f;
    sfr[tid] = l; sir[tid] = cnt; __syncthreads();
    for (int o = 128; o > 0; o >>= 1) {
        if (tid < o) { sfr[tid] += sfr[tid + o]; sir[tid] += sir[tid + o]; }
        __syncthreads();
    }
    if (tid == 0) {
        out[XYZ_OUT + NP_OUT]     = sfr[0] / (float)BQ;
        out[XYZ_OUT + NP_OUT + 1] = (float)sir[0];
    }
}

// ---------------- launch ----------------
static inline float* symf(const void* sym) { void* p = nullptr; cudaGetSymbolAddress(&p, sym); return (float*)p; }

extern "C" void kernel_launch(void* const* d_in, const int* in_sizes, int n_in,
                              void* d_out, int out_size)
{
    const float* xyz    = (const float*)d_in[0];
    const float* points = (const float*)d_in[1];
    const float* w1_w = (const float*)d_in[2];
    const float* w1_b = (const float*)d_in[3];
    const float* bn1g = (const float*)d_in[4];
    const float* bn1b = (const float*)d_in[5];
    const float* w2_w = (const float*)d_in[6];
    const float* w2_b = (const float*)d_in[7];
    const float* bn2g = (const float*)d_in[8];
    const float* bn2b = (const float*)d_in[9];
    const float* c0w = (const float*)d_in[10];
    const float* c0b = (const float*)d_in[11];
    const float* g0  = (const float*)d_in[12];
    const float* b0  = (const float*)d_in[13];
    const float* c1w = (const float*)d_in[14];
    const float* c1b = (const float*)d_in[15];
    const float* g1  = (const float*)d_in[16];
    const float* b1  = (const float*)d_in[17];
    const float* c2w = (const float*)d_in[18];
    const float* c2b = (const float*)d_in[19];
    const float* g2  = (const float*)d_in[20];
    const float* b2  = (const float*)d_in[21];
    float* out = (float*)d_out;

    float* p_agg  = symf(g_agg);
    float* p_h1   = symf(g_h1);
    float* p_h2   = symf(g_h2);
    float* p_selT = symf(g_selT);
    float* p_inner= symf(g_inner);
    float* p_ptst = symf(g_ptst);
    float* p_xyzt = symf(g_xyzt);
    float* p_Bmat = symf(g_Bmat);
    float* p_C    = symf(g_Cbig);
    float* p_E    = symf(g_E);
    float* p_O0   = symf(g_O0);
    float* p_O1   = symf(g_O1);
    float* p_O2   = symf(g_O2);
    float* p_s1   = symf(g_s1);
    float* p_sh1  = symf(g_sh1);
    float* p_s2   = symf(g_s2);
    float* p_sh2  = symf(g_sh2);
    float* p_sc0  = symf(g_sc0);
    float* p_sf0  = symf(g_sf0);
    float* p_sc1  = symf(g_sc1);
    float* p_sf1  = symf(g_sf1);
    float* p_sc2  = symf(g_sc2);
    float* p_sf2  = symf(g_sf2);

    sa_init<<<9, 256>>>();

    // agg = concat(points, xyz) channel-major
    sa_agg<<<(int)(((size_t)BQ*SCQ*NQ + 255) / 256), 256>>>(points, xyz);
    // transposes for gather
    sa_tr<<<(int)(((size_t)BQ*NQ*DQ + 255) / 256), 256>>>(points, p_ptst, DQ);
    sa_tr<<<(int)(((size_t)BQ*NQ*3 + 255) / 256), 256>>>(xyz, p_xyzt, 3);
    // ball query
    sa_ball<<<(BQ * NQ * 32) / 256, 256>>>(xyz);

    // h1 = w1 @ agg + b1
    sa_gemm<<<dim3(16, 1, BQ), 256>>>(w1_w, p_agg, p_h1, SCQ, NQ, SCQ,
                                      0, (size_t)SCQ*NQ, (size_t)SCQ*NQ, w1_b, nullptr, nullptr);
    sa_stats<<<SCQ, 256>>>(p_h1, SCQ, NQ, bn1g, bn1b, p_s1, p_sh1);
    sa_bnapply<<<(int)(((size_t)BQ*SCQ*NQ + 255) / 256), 256>>>(p_h1, p_s1, p_sh1, SCQ, NQ);

    // h2 = w2 @ h1 + b2
    sa_gemm<<<dim3(16, 4, BQ), 256>>>(w2_w, p_h1, p_h2, SQ, NQ, SCQ,
                                      0, (size_t)SCQ*NQ, (size_t)SQ*NQ, w2_b, nullptr, nullptr);
    sa_stats<<<SQ, 256>>>(p_h2, SQ, NQ, bn2g, bn2b, p_s2, p_sh2);
    // softmax(bn2(h2)) in place -> select; also norms + argmax(b=0)
    sa_softmax<<<dim3(SQ, BQ), 256>>>(p_h2);
    sa_flags<<<2, 256>>>();

    // cosine loss: inner = S S^T
    sa_selT<<<dim3(NQ / 32, SQ / 32, BQ), dim3(32, 8)>>>();
    sa_gemm<<<dim3(4, 4, BQ), 256>>>(p_h2, p_selT, p_inner, SQ, SQ, NQ,
                                     (size_t)SQ*NQ, (size_t)NQ*SQ, (size_t)SQ*SQ,
                                     nullptr, nullptr, nullptr);
    sa_cos_epi<<<(int)(((size_t)BQ*SQ*SQ) / 256), 256>>>();

    // grouped feature matrix + big GEMM
    sa_bmat<<<dim3(NQ, BQ), 256>>>();
    sa_gemm<<<dim3((JQ + 127) / 128, 4, BQ), 256>>>(p_h2, p_Bmat, p_C, SQ, JQ, NQ,
                                                    (size_t)SQ*NQ, (size_t)NQ*JQ, (size_t)SQ*JQ,
                                                    nullptr, nullptr, nullptr);
    sa_newxyz<<<(BQ*3*SQ + 255) / 256, 256>>>(out);
    sa_edge<<<(int)(((size_t)BQ*INCH*KSQ + 255) / 256), 256>>>();

    // conv stack
    sa_gemm<<<dim3(KSQ / 128, 1, BQ), 256>>>(c0w, p_E, p_O0, C0Q, KSQ, INCH,
                                             0, (size_t)INCH*KSQ, (size_t)C0Q*KSQ, c0b, nullptr, nullptr);
    sa_stats<<<C0Q, 256>>>(p_O0, C0Q, KSQ, g0, b0, p_sc0, p_sf0);
    sa_gemm<<<dim3(KSQ / 128, 1, BQ), 256>>>(c1w, p_O0, p_O1, C1Q, KSQ, C0Q,
                                             0, (size_t)C0Q*KSQ, (size_t)C1Q*KSQ, c1b, p_sc0, p_sf0);
    sa_stats<<<C1Q, 256>>>(p_O1, C1Q, KSQ, g1, b1, p_sc1, p_sf1);
    sa_gemm<<<dim3(KSQ / 128, 2, BQ), 256>>>(c2w, p_O1, p_O2, C2Q, KSQ, C1Q,
                                             0, (size_t)C1Q*KSQ, (size_t)C2Q*KSQ, c2b, p_sc1, p_sf1);
    sa_stats<<<C2Q, 256>>>(p_O2, C2Q, KSQ, g2, b2, p_sc2, p_sf2);

    // BN+leaky+max over k -> new_points
    sa_max<<<(int)((NP_OUT + 255) / 256), 256>>>(out);
    // scalars
    sa_scalars<<<1, 256>>>(out);
}

// round 4
// speedup vs baseline: 1.1806x; 1.1806x over previous
#include <cuda_runtime.h>
#include <cuda_bf16.h>
#include <math.h>
#include <stdint.h>

#define BQ 16
#define NQ 2048
#define DQ 64
#define SQ 512
#define NSQ 32
#define SCQ 67
#define INCH 134
#define C0Q 128
#define C1Q 128
#define C2Q 256
#define KSQ (NSQ*SQ)
#define JQ (3+DQ+NSQ*DQ+NSQ*3)   // 2211
#define OFF_X 0
#define OFF_P 3
#define OFF_GP 67
#define OFF_GX 2115
#define XYZ_OUT (BQ*3*SQ)
#define NP_OUT  ((size_t)BQ*C2Q*SQ)

// ---------------- scratch ----------------
__device__ float g_aggT[(size_t)BQ*NQ*SCQ];
__device__ float g_h1t [(size_t)BQ*NQ*SCQ];
__device__ float g_h2  [(size_t)BQ*SQ*NQ];
__device__ float g_inner[(size_t)BQ*SQ*SQ];
__device__ float g_norm[BQ*SQ];
__device__ int   g_amax[SQ];
__device__ int   g_idx[(size_t)BQ*NSQ*NQ];   // (b,k,n)
__device__ float g_BmT [(size_t)BQ*JQ*NQ];
__device__ float g_Cbig[(size_t)BQ*SQ*JQ];
__device__ float g_ET  [(size_t)BQ*KSQ*INCH];
__device__ float g_O0T [(size_t)BQ*KSQ*C0Q];
__device__ float g_O1T [(size_t)BQ*KSQ*C1Q];
__device__ float g_O2T [(size_t)BQ*KSQ*C2Q];
__device__ double g_part[(size_t)256*256*2];
__device__ float g_s1[SCQ], g_sh1[SCQ];
__device__ float g_s2[SQ],  g_sh2[SQ];
__device__ float g_sc0[C0Q], g_sf0[C0Q];
__device__ float g_sc1[C1Q], g_sf1[C1Q];
__device__ float g_sc2[C2Q], g_sf2[C2Q];
__device__ float g_acc[BQ];
__device__ int   g_flags[NQ];

// ---------------- mma helpers ----------------
__device__ __forceinline__ uint32_t smem_u32(const void* p) {
    uint32_t a;
    asm("{ .reg .u64 t; cvta.to.shared.u64 t, %1; cvt.u32.u64 %0, t; }" : "=r"(a) : "l"(p));
    return a;
}
__device__ __forceinline__ void ldm4(uint32_t* r, uint32_t addr) {
    asm volatile("ldmatrix.sync.aligned.m8n8.x4.shared.b16 {%0,%1,%2,%3}, [%4];"
        : "=r"(r[0]), "=r"(r[1]), "=r"(r[2]), "=r"(r[3]) : "r"(addr));
}
__device__ __forceinline__ void mma16816(float* c, const uint32_t* a, const uint32_t* b) {
    asm volatile("mma.sync.aligned.m16n8k16.row.col.f32.bf16.bf16.f32 "
        "{%0,%1,%2,%3}, {%4,%5,%6,%7}, {%8,%9}, {%0,%1,%2,%3};"
        : "+f"(c[0]), "+f"(c[1]), "+f"(c[2]), "+f"(c[3])
        : "r"(a[0]), "r"(a[1]), "r"(a[2]), "r"(a[3]), "r"(b[0]), "r"(b[1]));
}

// ---------------- HMMA GEMM: C[b](MxN) = A[b](MxK) * Bt[b](NxK)^T ----------------
// fp32 in/out, bf16 hi/lo split (3 passes). M % 128 == 0. Optional per-K affine
// (+leaky 0.2) on A or B; row/col bias on output.
#define RSH 40   // smem row stride in halves (80 B, 16B-aligned, conflict-free ldmatrix)
__global__ void __launch_bounds__(256) mma_gemm(
    const float* __restrict__ A, const float* __restrict__ Bt, float* __restrict__ C,
    int M, int N, int K, size_t sA, size_t sB, size_t sC,
    const float* __restrict__ biasRow, const float* __restrict__ biasCol,
    const float* __restrict__ scA, const float* __restrict__ shA, int lkA,
    const float* __restrict__ scB, const float* __restrict__ shB)
{
    __shared__ __align__(16) uint16_t sAh[128*RSH], sAl[128*RSH];
    __shared__ __align__(16) uint16_t sBh[128*RSH], sBl[128*RSH];
    const int tid = threadIdx.x;
    const int w = tid >> 5, lane = tid & 31;
    const int wm = w & 1, wn = w >> 1;          // 2x4 warp grid: 64x32 per warp
    const int m0 = blockIdx.y * 128, n0 = blockIdx.x * 128, b = blockIdx.z;
    const float* Ab = A + (size_t)b * sA;
    const float* Bb = Bt + (size_t)b * sB;

    float acc[4][4][4];
    #pragma unroll
    for (int i = 0; i < 4; i++)
        #pragma unroll
        for (int j = 0; j < 4; j++)
            #pragma unroll
            for (int q = 0; q < 4; q++) acc[i][j][q] = 0.f;

    const uint32_t uAh = smem_u32(sAh), uAl = smem_u32(sAl);
    const uint32_t uBh = smem_u32(sBh), uBl = smem_u32(sBl);

    const int T = (K + 31) >> 5;
    for (int t = 0; t < T; t++) {
        const int k0 = t << 5;
        #pragma unroll
        for (int op = 0; op < 2; op++) {
            const float* S = op ? Bb : Ab;
            const int r0 = op ? n0 : m0;
            const int rmax = op ? N : M;
            const float* scp = op ? scB : scA;
            const float* shp = op ? shB : shA;
            const int lk = op ? 0 : lkA;
            uint16_t* hi = op ? sBh : sAh;
            uint16_t* lo = op ? sBl : sAl;
            #pragma unroll
            for (int i = 0; i < 8; i++) {
                int e = tid + i * 256;
                int r = e >> 4, cw = e & 15;
                int rg = r0 + r, kk = k0 + (cw << 1);
                float v0 = 0.f, v1 = 0.f;
                if (rg < rmax) {
                    if (kk < K)     v0 = S[(size_t)rg * K + kk];
                    if (kk + 1 < K) v1 = S[(size_t)rg * K + kk + 1];
                    if (scp) {
                        if (kk < K)     { v0 = scp[kk]*v0 + shp[kk];     if (lk && v0 < 0.f) v0 *= 0.2f; }
                        if (kk + 1 < K) { v1 = scp[kk+1]*v1 + shp[kk+1]; if (lk && v1 < 0.f) v1 *= 0.2f; }
                    }
                }
                __nv_bfloat16 h0 = __float2bfloat16(v0), h1 = __float2bfloat16(v1);
                __nv_bfloat16 l0 = __float2bfloat16(v0 - __bfloat162float(h0));
                __nv_bfloat16 l1 = __float2bfloat16(v1 - __bfloat162float(h1));
                uint32_t hwd = ((uint32_t)__bfloat16_as_ushort(h1) << 16) | __bfloat16_as_ushort(h0);
                uint32_t lwd = ((uint32_t)__bfloat16_as_ushort(l1) << 16) | __bfloat16_as_ushort(l0);
                int off = r * RSH + (cw << 1);
                *(uint32_t*)&hi[off] = hwd;
                *(uint32_t*)&lo[off] = lwd;
            }
        }
        __syncthreads();
        #pragma unroll
        for (int k16 = 0; k16 < 32; k16 += 16) {
            uint32_t ah[4][4], al[4][4], bh[4][2], bl[4][2];
            {
                int arow = wm * 64 + (lane & 15);
                int akk = k16 + ((lane >> 4) << 3);
                #pragma unroll
                for (int mf = 0; mf < 4; mf++) {
                    uint32_t byteoff = (uint32_t)(((arow + mf * 16) * RSH + akk) << 1);
                    ldm4(ah[mf], uAh + byteoff);
                    ldm4(al[mf], uAl + byteoff);
                }
                int q = lane >> 3;
                int brow0 = wn * 32 + ((q >> 1) << 3) + (lane & 7);
                int bkk = k16 + ((q & 1) << 3);
                #pragma unroll
                for (int p = 0; p < 2; p++) {
                    uint32_t byteoff = (uint32_t)(((brow0 + p * 16) * RSH + bkk) << 1);
                    uint32_t tmp[4];
                    ldm4(tmp, uBh + byteoff);
                    bh[2*p][0] = tmp[0]; bh[2*p][1] = tmp[1];
                    bh[2*p+1][0] = tmp[2]; bh[2*p+1][1] = tmp[3];
                    ldm4(tmp, uBl + byteoff);
                    bl[2*p][0] = tmp[0]; bl[2*p][1] = tmp[1];
                    bl[2*p+1][0] = tmp[2]; bl[2*p+1][1] = tmp[3];
                }
            }
            #pragma unroll
            for (int mf = 0; mf < 4; mf++)
                #pragma unroll
                for (int nf = 0; nf < 4; nf++) {
                    mma16816(acc[mf][nf], ah[mf], bh[nf]);
                    mma16816(acc[mf][nf], ah[mf], bl[nf]);
                    mma16816(acc[mf][nf], al[mf], bh[nf]);
                }
        }
        __syncthreads();
    }

    // epilogue
    float* Cb = C + (size_t)b * sC;
    #pragma unroll
    for (int mf = 0; mf < 4; mf++) {
        int r = m0 + wm * 64 + mf * 16 + (lane >> 2);
        float br0 = biasRow ? biasRow[r] : 0.f;
        float br1 = biasRow ? biasRow[r + 8] : 0.f;
        #pragma unroll
        for (int nf = 0; nf < 4; nf++) {
            int c = n0 + wn * 32 + nf * 8 + ((lane & 3) << 1);
            #pragma unroll
            for (int u = 0; u < 2; u++) {
                int col = c + u;
                if (col < N) {
                    float bc = biasCol ? biasCol[col] : 0.f;
                    Cb[(size_t)r * N + col]       = acc[mf][nf][u]     + br0 + bc;
                    Cb[(size_t)(r + 8) * N + col] = acc[mf][nf][u + 2] + br1 + bc;
                }
            }
        }
    }
}

// ---------------- helpers ----------------
__global__ void sa_init() {
    int i = blockIdx.x * 256 + threadIdx.x;
    if (i < NQ) g_flags[i] = 0;
    if (i < BQ) g_acc[i] = 0.f;
}

__global__ void sa_aggT(const float* __restrict__ points, const float* __restrict__ xyz) {
    size_t i = (size_t)blockIdx.x * 256 + threadIdx.x;
    if (i >= (size_t)BQ*NQ*SCQ) return;
    int c = (int)(i % SCQ); size_t r = i / SCQ; int n = (int)(r % NQ); int b = (int)(r / NQ);
    g_aggT[i] = (c < DQ) ? points[((size_t)b*DQ + c)*NQ + n] : xyz[((size_t)b*3 + (c-DQ))*NQ + n];
}

// ball query -> g_idx (b,k,n)
__global__ void sa_ball(const float* __restrict__ xyz) {
    int w = (blockIdx.x * blockDim.x + threadIdx.x) >> 5;
    int lane = threadIdx.x & 31;
    if (w >= BQ * NQ) return;
    int b = w / NQ, n = w % NQ;
    const float* X = xyz + (size_t)b * 3 * NQ;
    float px = X[n], py = X[NQ+n], pz = X[2*NQ+n];
    float pn = px*px + py*py + pz*pz;
    const float RR = (float)(0.2 * 0.2);
    int* out = g_idx + (size_t)b * NSQ * NQ + n;
    int cnt = 0;
    for (int j0 = 0; j0 < NQ && cnt < NSQ; j0 += 32) {
        int j = j0 + lane;
        float qx = X[j], qy = X[NQ+j], qz = X[2*NQ+j];
        float sq = (pn + qx*qx+qy*qy+qz*qz) - 2.0f*(px*qx+py*qy+pz*qz);
        bool in = !(sq > RR);
        unsigned m = __ballot_sync(0xffffffffu, in);
        int pos = cnt + __popc(m & ((1u << lane) - 1u));
        if (in && pos < NSQ) out[(size_t)pos * NQ] = j;
        cnt += __popc(m);
    }
    __syncwarp();
    if (lane == 0) {
        int first = out[0];
        for (int t = cnt; t < NSQ; t++) out[(size_t)t * NQ] = first;
    }
}

// column-channel BN stats
__global__ void sa_cs_part(const float* __restrict__ X, int C, int totalRows, int rpc) {
    int chunk = blockIdx.x, tid = threadIdx.x;
    if (tid >= C) return;
    double s = 0.0, s2 = 0.0;
    int r1 = min((chunk + 1) * rpc, totalRows);
    for (int r = chunk * rpc; r < r1; r++) {
        double v = X[(size_t)r * C + tid];
        s += v; s2 += v * v;
    }
    g_part[((size_t)chunk * C + tid) * 2] = s;
    g_part[((size_t)chunk * C + tid) * 2 + 1] = s2;
}
__global__ void sa_cs_fin(int C, int nChunks, int count,
                          const float* __restrict__ gamma, const float* __restrict__ beta,
                          float* __restrict__ sc, float* __restrict__ sf) {
    int c = blockIdx.x, tid = threadIdx.x;
    double s = 0.0, s2 = 0.0;
    for (int i = tid; i < nChunks; i += 256) {
        s  += g_part[((size_t)i * C + c) * 2];
        s2 += g_part[((size_t)i * C + c) * 2 + 1];
    }
    __shared__ double sa[256], sb2[256];
    sa[tid] = s; sb2[tid] = s2; __syncthreads();
    for (int o = 128; o > 0; o >>= 1) {
        if (tid < o) { sa[tid] += sa[tid+o]; sb2[tid] += sb2[tid+o]; }
        __syncthreads();
    }
    if (tid == 0) {
        double n = (double)count, m = sa[0] / n;
        double var = sb2[0] / n - m * m; if (var < 0.0) var = 0.0;
        float scale = gamma[c] * rsqrtf((float)var + 1e-5f);
        sc[c] = scale; sf[c] = beta[c] - (float)m * scale;
    }
}

// row-channel BN stats for h2
__global__ void sa_rstats(const float* __restrict__ X, int Cch, int L,
                          const float* __restrict__ gamma, const float* __restrict__ beta,
                          float* __restrict__ sc, float* __restrict__ sf) {
    int c = blockIdx.x, tid = threadIdx.x;
    double s = 0.0, s2 = 0.0;
    for (int b = 0; b < BQ; b++) {
        const float* p = X + ((size_t)b * Cch + c) * L;
        for (int i = tid; i < L; i += 256) { double v = p[i]; s += v; s2 += v * v; }
    }
    __shared__ double ss[256], ss2[256];
    ss[tid] = s; ss2[tid] = s2; __syncthreads();
    for (int o = 128; o > 0; o >>= 1) {
        if (tid < o) { ss[tid] += ss[tid+o]; ss2[tid] += ss2[tid+o]; }
        __syncthreads();
    }
    if (tid == 0) {
        double n = (double)BQ * L, m = ss[0] / n;
        double var = ss2[0] / n - m * m; if (var < 0.0) var = 0.0;
        float scale = gamma[c] * rsqrtf((float)var + 1e-5f);
        sc[c] = scale; sf[c] = beta[c] - (float)m * scale;
    }
}

// softmax (applies bn2 affine) in place; norms + argmax(b=0)
__global__ void sa_softmax(float* __restrict__ H) {
    int s = blockIdx.x, b = blockIdx.y, tid = threadIdx.x;
    float* row = H + ((size_t)b * SQ + s) * NQ;
    __shared__ float buf[NQ];
    __shared__ float red[256], rv[256];
    __shared__ int ri[256];
    float a = g_s2[s], sh = g_sh2[s];
    float lmax = -3.4e38f;
    for (int i = tid; i < NQ; i += 256) { float y = a*row[i]+sh; buf[i] = y; lmax = fmaxf(lmax, y); }
    red[tid] = lmax; __syncthreads();
    for (int o = 128; o > 0; o >>= 1) { if (tid < o) red[tid] = fmaxf(red[tid], red[tid+o]); __syncthreads(); }
    float gmax = red[0]; __syncthreads();
    float lsum = 0.f;
    for (int i = tid; i < NQ; i += 256) { float e = expf(buf[i]-gmax); buf[i] = e; lsum += e; }
    red[tid] = lsum; __syncthreads();
    for (int o = 128; o > 0; o >>= 1) { if (tid < o) red[tid] += red[tid+o]; __syncthreads(); }
    float inv = 1.f / red[0]; __syncthreads();
    float lss = 0.f, bm = -1.f; int bi = 0;
    for (int i = tid; i < NQ; i += 256) {
        float v = buf[i] * inv; row[i] = v; lss += v*v;
        if (v > bm) { bm = v; bi = i; }
    }
    red[tid] = lss; rv[tid] = bm; ri[tid] = bi; __syncthreads();
    for (int o = 128; o > 0; o >>= 1) {
        if (tid < o) {
            red[tid] += red[tid+o];
            if (rv[tid+o] > rv[tid] || (rv[tid+o] == rv[tid] && ri[tid+o] < ri[tid])) { rv[tid] = rv[tid+o]; ri[tid] = ri[tid+o]; }
        }
        __syncthreads();
    }
    if (tid == 0) {
        g_norm[b*SQ+s] = sqrtf(red[0]);
        if (b == 0) g_amax[s] = ri[0];
    }
}

__global__ void sa_flags() { int s = blockIdx.x*256 + threadIdx.x; if (s < SQ) g_flags[g_amax[s]] = 1; }

__global__ void sa_cos_epi() {
    size_t i = (size_t)blockIdx.x * 256 + threadIdx.x;
    int b = (int)(i / ((size_t)SQ*SQ)), r = (int)((i / SQ) % SQ), c = (int)(i % SQ);
    float v = 0.f;
    if (r != c) {
        float cm = g_inner[i] / (g_norm[b*SQ+r] * g_norm[b*SQ+c] + 1e-10f);
        v = cm * cm;
    }
    __shared__ float red[256];
    red[threadIdx.x] = v; __syncthreads();
    for (int o = 128; o > 0; o >>= 1) { if (threadIdx.x < o) red[threadIdx.x] += red[threadIdx.x+o]; __syncthreads(); }
    if (threadIdx.x == 0) atomicAdd(&g_acc[b], red[0]);
}

// BmT (b, j, n)
__global__ void sa_bmt(const float* __restrict__ points, const float* __restrict__ xyz) {
    size_t i = (size_t)blockIdx.x * 256 + threadIdx.x;
    if (i >= (size_t)BQ*JQ*NQ) return;
    int n = (int)(i % NQ); size_t r = i / NQ; int j = (int)(r % JQ); int b = (int)(r / JQ);
    float v;
    if (j < OFF_P) v = xyz[((size_t)b*3 + j)*NQ + n];
    else if (j < OFF_GP) v = points[((size_t)b*DQ + (j-OFF_P))*NQ + n];
    else if (j < OFF_GX) {
        int t = j - OFF_GP, k = t >> 6, d = t & 63;
        int ii = g_idx[((size_t)b*NSQ + k)*NQ + n];
        v = points[((size_t)b*DQ + d)*NQ + ii];
    } else {
        int t = j - OFF_GX, k = t / 3, c = t % 3;
        int ii = g_idx[((size_t)b*NSQ + k)*NQ + n];
        v = xyz[((size_t)b*3 + c)*NQ + ii];
    }
    g_BmT[i] = v;
}

__global__ void sa_newxyz(float* __restrict__ out) {
    int i = blockIdx.x * 256 + threadIdx.x;
    if (i >= BQ*3*SQ) return;
    int s = i % SQ, c = (i/SQ) % 3, b = i/(3*SQ);
    out[i] = g_Cbig[((size_t)b*SQ + s)*JQ + OFF_X + c];
}

// ET (b, k*SQ+s, ch)
__global__ void sa_et() {
    size_t i = (size_t)blockIdx.x * 256 + threadIdx.x;
    if (i >= (size_t)BQ*KSQ*INCH) return;
    int ch = (int)(i % INCH); size_t r = i / INCH;
    int s = (int)(r % SQ); int k = (int)((r / SQ) % NSQ); int b = (int)(r / KSQ);
    const float* Cr = g_Cbig + ((size_t)b*SQ + s)*JQ;
    float v;
    if (ch < 64) v = Cr[OFF_P + ch];
    else if (ch < 128) { int d = ch - 64; v = Cr[OFF_GP + k*DQ + d] - Cr[OFF_P + d]; }
    else if (ch < 131) v = Cr[OFF_X + (ch - 128)];
    else { int c3 = ch - 131; v = Cr[OFF_GX + k*3 + c3] - Cr[OFF_X + c3]; }
    g_ET[i] = v;
}

// max over k of leaky(bn2(O2T))
__global__ void sa_max(float* __restrict__ out) {
    int s = blockIdx.x, b = blockIdx.y, o = threadIdx.x;
    float sc = g_sc2[o], sf = g_sf2[o];
    float m = -3.4e38f;
    const float* base = g_O2T + ((size_t)b*KSQ + s)*C2Q + o;
    #pragma unroll
    for (int k = 0; k < NSQ; k++) {
        float y = sc * base[(size_t)k*SQ*C2Q] + sf;
        y = (y >= 0.f) ? y : 0.2f * y;
        m = fmaxf(m, y);
    }
    out[XYZ_OUT + ((size_t)b*C2Q + o)*SQ + s] = m;
}

__global__ void sa_scalars(float* __restrict__ out) {
    __shared__ float sfr[256]; __shared__ int sir[256];
    int tid = threadIdx.x;
    int cnt = 0;
    for (int i = tid; i < NQ; i += 256) cnt += g_flags[i];
    float l = (tid < BQ) ? sqrtf(g_acc[tid]) : 0.f;
    sfr[tid] = l; sir[tid] = cnt; __syncthreads();
    for (int o = 128; o > 0; o >>= 1) {
        if (tid < o) { sfr[tid] += sfr[tid+o]; sir[tid] += sir[tid+o]; }
        __syncthreads();
    }
    if (tid == 0) {
        out[XYZ_OUT + NP_OUT] = sfr[0] / (float)BQ;
        out[XYZ_OUT + NP_OUT + 1] = (float)sir[0];
    }
}

// ---------------- launch ----------------
static inline float* symf(const void* sym) { void* p = nullptr; cudaGetSymbolAddress(&p, sym); return (float*)p; }

extern "C" void kernel_launch(void* const* d_in, const int* in_sizes, int n_in,
                              void* d_out, int out_size)
{
    const float* xyz   = (const float*)d_in[0];
    const float* points= (const float*)d_in[1];
    const float* w1_w = (const float*)d_in[2];
    const float* w1_b = (const float*)d_in[3];
    const float* bn1g = (const float*)d_in[4];
    const float* bn1b = (const float*)d_in[5];
    const float* w2_w = (const float*)d_in[6];
    const float* w2_b = (const float*)d_in[7];
    const float* bn2g = (const float*)d_in[8];
    const float* bn2b = (const float*)d_in[9];
    const float* c0w = (const float*)d_in[10];
    const float* c0b = (const float*)d_in[11];
    const float* g0  = (const float*)d_in[12];
    const float* b0  = (const float*)d_in[13];
    const float* c1w = (const float*)d_in[14];
    const float* c1b = (const float*)d_in[15];
    const float* g1  = (const float*)d_in[16];
    const float* b1  = (const float*)d_in[17];
    const float* c2w = (const float*)d_in[18];
    const float* c2b = (const float*)d_in[19];
    const float* g2  = (const float*)d_in[20];
    const float* b2  = (const float*)d_in[21];
    float* out = (float*)d_out;

    float* p_aggT = symf(g_aggT);
    float* p_h1t  = symf(g_h1t);
    float* p_h2   = symf(g_h2);
    float* p_inner= symf(g_inner);
    float* p_BmT  = symf(g_BmT);
    float* p_C    = symf(g_Cbig);
    float* p_ET   = symf(g_ET);
    float* p_O0   = symf(g_O0T);
    float* p_O1   = symf(g_O1T);
    float* p_O2   = symf(g_O2T);
    float* p_s1 = symf(g_s1),  *p_sh1 = symf(g_sh1);
    float* p_s2 = symf(g_s2),  *p_sh2 = symf(g_sh2);
    float* p_sc0 = symf(g_sc0), *p_sf0 = symf(g_sf0);
    float* p_sc1 = symf(g_sc1), *p_sf1 = symf(g_sf1);
    float* p_sc2 = symf(g_sc2), *p_sf2 = symf(g_sf2);

    sa_init<<<9, 256>>>();
    sa_aggT<<<(int)(((size_t)BQ*NQ*SCQ + 255)/256), 256>>>(points, xyz);
    sa_ball<<<(BQ*NQ*32)/256, 256>>>(xyz);
    sa_bmt<<<(int)(((size_t)BQ*JQ*NQ + 255)/256), 256>>>(points, xyz);

    // h1t (b, 2048 x 67) = aggT * w1^T + w1_b(col)
    mma_gemm<<<dim3(1, NQ/128, BQ), 256>>>(p_aggT, w1_w, p_h1t, NQ, SCQ, SCQ,
        (size_t)NQ*SCQ, 0, (size_t)NQ*SCQ, nullptr, w1_b, nullptr, nullptr, 0, nullptr, nullptr);
    sa_cs_part<<<128, 128>>>(p_h1t, SCQ, BQ*NQ, BQ*NQ/128);
    sa_cs_fin<<<SCQ, 256>>>(SCQ, 128, BQ*NQ, bn1g, bn1b, p_s1, p_sh1);

    // h2 (b, 512 x 2048) = w2 * bn1(h1t)^T + w2_b(row)
    mma_gemm<<<dim3(NQ/128, SQ/128, BQ), 256>>>(w2_w, p_h1t, p_h2, SQ, NQ, SCQ,
        0, (size_t)NQ*SCQ, (size_t)SQ*NQ, w2_b, nullptr, nullptr, nullptr, 0, p_s1, p_sh1);
    sa_rstats<<<SQ, 256>>>(p_h2, SQ, NQ, bn2g, bn2b, p_s2, p_sh2);
    sa_softmax<<<dim3(SQ, BQ), 256>>>(p_h2);
    sa_flags<<<2, 256>>>();

    // inner = S * S^T
    mma_gemm<<<dim3(SQ/128, SQ/128, BQ), 256>>>(p_h2, p_h2, p_inner, SQ, SQ, NQ,
        (size_t)SQ*NQ, (size_t)SQ*NQ, (size_t)SQ*SQ, nullptr, nullptr, nullptr, nullptr, 0, nullptr, nullptr);
    sa_cos_epi<<<(int)(((size_t)BQ*SQ*SQ)/256), 256>>>();

    // Cbig (b, 512 x 2211) = S * BmT^T
    mma_gemm<<<dim3((JQ+127)/128, SQ/128, BQ), 256>>>(p_h2, p_BmT, p_C, SQ, JQ, NQ,
        (size_t)SQ*NQ, (size_t)JQ*NQ, (size_t)SQ*JQ, nullptr, nullptr, nullptr, nullptr, 0, nullptr, nullptr);
    sa_newxyz<<<(BQ*3*SQ + 255)/256, 256>>>(out);
    sa_et<<<(int)(((size_t)BQ*KSQ*INCH + 255)/256), 256>>>();

    // conv stack (transposed): OiT (b, 16384 x Ci)
    mma_gemm<<<dim3(1, KSQ/128, BQ), 256>>>(p_ET, c0w, p_O0, KSQ, C0Q, INCH,
        (size_t)KSQ*INCH, 0, (size_t)KSQ*C0Q, nullptr, c0b, nullptr, nullptr, 0, nullptr, nullptr);
    sa_cs_part<<<256, 128>>>(p_O0, C0Q, BQ*KSQ, BQ*KSQ/256);
    sa_cs_fin<<<C0Q, 256>>>(C0Q, 256, BQ*KSQ, g0, b0, p_sc0, p_sf0);

    mma_gemm<<<dim3(1, KSQ/128, BQ), 256>>>(p_O0, c1w, p_O1, KSQ, C1Q, C0Q,
        (size_t)KSQ*C0Q, 0, (size_t)KSQ*C1Q, nullptr, c1b, p_sc0, p_sf0, 1, nullptr, nullptr);
    sa_cs_part<<<256, 128>>>(p_O1, C1Q, BQ*KSQ, BQ*KSQ/256);
    sa_cs_fin<<<C1Q, 256>>>(C1Q, 256, BQ*KSQ, g1, b1, p_sc1, p_sf1);

    mma_gemm<<<dim3(C2Q/128, KSQ/128, BQ), 256>>>(p_O1, c2w, p_O2, KSQ, C2Q, C1Q,
        (size_t)KSQ*C1Q, 0, (size_t)KSQ*C2Q, nullptr, c2b, p_sc1, p_sf1, 1, nullptr, nullptr);
    sa_cs_part<<<256, 256>>>(p_O2, C2Q, BQ*KSQ, BQ*KSQ/256);
    sa_cs_fin<<<C2Q, 256>>>(C2Q, 256, BQ*KSQ, g2, b2, p_sc2, p_sf2);

    sa_max<<<dim3(SQ, BQ), 256>>>(out);
    sa_scalars<<<1, 256>>>(out);
}

// round 5
// speedup vs baseline: 2.8183x; 2.3871x over previous
#include <cuda_runtime.h>
#include <cuda_bf16.h>
#include <math.h>
#include <stdint.h>

#define BQ 16
#define NQ 2048
#define DQ 64
#define SQ 512
#define NSQ 32
#define SCQ 67
#define INCH 134
#define C0Q 128
#define C1Q 128
#define C2Q 256
#define KSQ (NSQ*SQ)
#define JQ (3+DQ+NSQ*DQ+NSQ*3)   // 2211
#define OFF_X 0
#define OFF_P 3
#define OFF_GP 67
#define OFF_GX 2115
#define XYZ_OUT (BQ*3*SQ)
#define NP_OUT  ((size_t)BQ*C2Q*SQ)
#define KP1 96    // padded K for 67
#define KPE 160   // padded K for 134

typedef unsigned short ush;

// ---------------- fp32 scratch ----------------
__device__ float g_h1t [(size_t)BQ*NQ*SCQ];
__device__ float g_h2  [(size_t)BQ*SQ*NQ];
__device__ float g_inner[(size_t)BQ*SQ*SQ];
__device__ float g_Cbig[(size_t)BQ*SQ*JQ];
__device__ float g_O0T [(size_t)BQ*KSQ*C0Q];
__device__ float g_O1T [(size_t)BQ*KSQ*C1Q];
__device__ float g_O2T [(size_t)BQ*KSQ*C2Q];
__device__ float g_norm[BQ*SQ];
__device__ int   g_amax[SQ];
__device__ int   g_idx[(size_t)BQ*NSQ*NQ];
__device__ double g_part[(size_t)256*256*2];
__device__ float g_s1[SCQ], g_sh1[SCQ];
__device__ float g_s2[SQ],  g_sh2[SQ];
__device__ float g_sc0[C0Q], g_sf0[C0Q];
__device__ float g_sc1[C1Q], g_sf1[C1Q];
__device__ float g_sc2[C2Q], g_sf2[C2Q];
__device__ float g_acc[BQ];
__device__ int   g_flags[NQ];

// ---------------- bf16 hi/lo operand arrays ----------------
__device__ ush g_aggc_h[(size_t)BQ*NQ*KP1],  g_aggc_l[(size_t)BQ*NQ*KP1];
__device__ ush g_w1c_h[SCQ*KP1],             g_w1c_l[SCQ*KP1];
__device__ ush g_h1c_h[(size_t)BQ*NQ*KP1],   g_h1c_l[(size_t)BQ*NQ*KP1];
__device__ ush g_w2c_h[SQ*KP1],              g_w2c_l[SQ*KP1];
__device__ ush g_Sc_h[(size_t)BQ*SQ*NQ],     g_Sc_l[(size_t)BQ*SQ*NQ];
__device__ ush g_BmTc_h[(size_t)BQ*JQ*NQ],   g_BmTc_l[(size_t)BQ*JQ*NQ];
__device__ ush g_ETc_h[(size_t)BQ*KSQ*KPE],  g_ETc_l[(size_t)BQ*KSQ*KPE];
__device__ ush g_c0wc_h[C0Q*KPE],            g_c0wc_l[C0Q*KPE];
__device__ ush g_c1wc_h[C1Q*C0Q],            g_c1wc_l[C1Q*C0Q];
__device__ ush g_c2wc_h[C2Q*C1Q],            g_c2wc_l[C2Q*C1Q];
__device__ ush g_O0c_h[(size_t)BQ*KSQ*C0Q],  g_O0c_l[(size_t)BQ*KSQ*C0Q];
__device__ ush g_O1c_h[(size_t)BQ*KSQ*C1Q],  g_O1c_l[(size_t)BQ*KSQ*C1Q];

// ---------------- helpers ----------------
__device__ __forceinline__ uint32_t smem_u32(const void* p) {
    uint32_t a;
    asm("{ .reg .u64 t; cvta.to.shared.u64 t, %1; cvt.u32.u64 %0, t; }" : "=r"(a) : "l"(p));
    return a;
}
__device__ __forceinline__ void ldm4(uint32_t* r, uint32_t addr) {
    asm volatile("ldmatrix.sync.aligned.m8n8.x4.shared.b16 {%0,%1,%2,%3}, [%4];"
        : "=r"(r[0]), "=r"(r[1]), "=r"(r[2]), "=r"(r[3]) : "r"(addr));
}
__device__ __forceinline__ void mma16816(float* c, const uint32_t* a, const uint32_t* b) {
    asm volatile("mma.sync.aligned.m16n8k16.row.col.f32.bf16.bf16.f32 "
        "{%0,%1,%2,%3}, {%4,%5,%6,%7}, {%8,%9}, {%0,%1,%2,%3};"
        : "+f"(c[0]), "+f"(c[1]), "+f"(c[2]), "+f"(c[3])
        : "r"(a[0]), "r"(a[1]), "r"(a[2]), "r"(a[3]), "r"(b[0]), "r"(b[1]));
}
__device__ __forceinline__ void split_write(float v, ush* ph, ush* pl) {
    __nv_bfloat16 h = __float2bfloat16(v);
    __nv_bfloat16 l = __float2bfloat16(v - __bfloat162float(h));
    *ph = __bfloat16_as_ushort(h);
    *pl = __bfloat16_as_ushort(l);
}

// ---------------- pipelined HMMA GEMM: C[b](MxN) = A[b](MxKp) * B[b](NxKp)^T ----
// Operands pre-split bf16 hi/lo. Kp % 32 == 0, M % 128 == 0. fp32 out + biases.
#define KC 32
#define RSH 40
#define TILEH (128*RSH)
#define STAGEH (4*TILEH)
#define SMEM_BYTES (2*STAGEH*2)   // 81920 B
__global__ void __launch_bounds__(256) mma_gemm(
    const ush* __restrict__ Ah, const ush* __restrict__ Al,
    const ush* __restrict__ Bh, const ush* __restrict__ Bl,
    float* __restrict__ C, int M, int N, int Kp,
    size_t sA, size_t sB, size_t sC,
    const float* __restrict__ biasRow, const float* __restrict__ biasCol)
{
    extern __shared__ ush sm[];
    const int tid = threadIdx.x;
    const int w = tid >> 5, lane = tid & 31;
    const int wm = w & 1, wn = w >> 1;
    const int m0 = blockIdx.y * 128, n0 = blockIdx.x * 128, b = blockIdx.z;
    const ush* srcs[4] = { Ah + (size_t)b*sA, Al + (size_t)b*sA,
                           Bh + (size_t)b*sB, Bl + (size_t)b*sB };
    const uint32_t smb = smem_u32(sm);

    float acc[4][4][4];
    #pragma unroll
    for (int i = 0; i < 4; i++)
        #pragma unroll
        for (int j = 0; j < 4; j++)
            #pragma unroll
            for (int q = 0; q < 4; q++) acc[i][j][q] = 0.f;

    const int T = Kp / KC;

    #define LOAD_STAGE(t, st) do { \
        int k0 = (t) * KC; \
        _Pragma("unroll") \
        for (int arr = 0; arr < 4; arr++) { \
            int r0 = (arr < 2) ? m0 : n0; \
            int rmax = (arr < 2) ? M : N; \
            const ush* S = srcs[arr]; \
            uint32_t dbase = smb + (uint32_t)(((st)*STAGEH + arr*TILEH) * 2); \
            _Pragma("unroll") \
            for (int i = 0; i < 2; i++) { \
                int e = tid + i * 256; \
                int r = e >> 2, c16 = e & 3; \
                uint32_t daddr = dbase + (uint32_t)((r * RSH + c16 * 8) * 2); \
                int rg = r0 + r; \
                int rc = rg < rmax ? rg : (rmax - 1); \
                const ush* sp = S + (size_t)rc * Kp + k0 + c16 * 8; \
                int sz = (rg < rmax) ? 16 : 0; \
                asm volatile("cp.async.cg.shared.global [%0], [%1], 16, %2;" \
                             :: "r"(daddr), "l"(sp), "r"(sz)); \
            } \
        } \
        asm volatile("cp.async.commit_group;" ::: "memory"); \
    } while (0)

    LOAD_STAGE(0, 0);
    for (int t = 0; t < T; t++) {
        const int st = t & 1;
        if (t + 1 < T) {
            LOAD_STAGE(t + 1, st ^ 1);
            asm volatile("cp.async.wait_group 1;" ::: "memory");
        } else {
            asm volatile("cp.async.wait_group 0;" ::: "memory");
        }
        __syncthreads();
        const uint32_t uAh = smb + (uint32_t)((st*STAGEH + 0*TILEH) * 2);
        const uint32_t uAl = smb + (uint32_t)((st*STAGEH + 1*TILEH) * 2);
        const uint32_t uBh = smb + (uint32_t)((st*STAGEH + 2*TILEH) * 2);
        const uint32_t uBl = smb + (uint32_t)((st*STAGEH + 3*TILEH) * 2);
        #pragma unroll
        for (int k16 = 0; k16 < 32; k16 += 16) {
            uint32_t ah[4][4], al[4][4], bh[4][2], bl[4][2];
            {
                int arow = wm * 64 + (lane & 15);
                int akk = k16 + ((lane >> 4) << 3);
                #pragma unroll
                for (int mf = 0; mf < 4; mf++) {
                    uint32_t byteoff = (uint32_t)(((arow + mf * 16) * RSH + akk) << 1);
                    ldm4(ah[mf], uAh + byteoff);
                    ldm4(al[mf], uAl + byteoff);
                }
                int q = lane >> 3;
                int brow0 = wn * 32 + ((q >> 1) << 3) + (lane & 7);
                int bkk = k16 + ((q & 1) << 3);
                #pragma unroll
                for (int p = 0; p < 2; p++) {
                    uint32_t byteoff = (uint32_t)(((brow0 + p * 16) * RSH + bkk) << 1);
                    uint32_t tmp[4];
                    ldm4(tmp, uBh + byteoff);
                    bh[2*p][0] = tmp[0]; bh[2*p][1] = tmp[1];
                    bh[2*p+1][0] = tmp[2]; bh[2*p+1][1] = tmp[3];
                    ldm4(tmp, uBl + byteoff);
                    bl[2*p][0] = tmp[0]; bl[2*p][1] = tmp[1];
                    bl[2*p+1][0] = tmp[2]; bl[2*p+1][1] = tmp[3];
                }
            }
            #pragma unroll
            for (int mf = 0; mf < 4; mf++)
                #pragma unroll
                for (int nf = 0; nf < 4; nf++)
                    mma16816(acc[mf][nf], ah[mf], bh[nf]);
            #pragma unroll
            for (int mf = 0; mf < 4; mf++)
                #pragma unroll
                for (int nf = 0; nf < 4; nf++)
                    mma16816(acc[mf][nf], ah[mf], bl[nf]);
            #pragma unroll
            for (int mf = 0; mf < 4; mf++)
                #pragma unroll
                for (int nf = 0; nf < 4; nf++)
                    mma16816(acc[mf][nf], al[mf], bh[nf]);
        }
        __syncthreads();
    }

    float* Cb = C + (size_t)b * sC;
    #pragma unroll
    for (int mf = 0; mf < 4; mf++) {
        int r = m0 + wm * 64 + mf * 16 + (lane >> 2);
        float br0 = biasRow ? biasRow[r] : 0.f;
        float br1 = biasRow ? biasRow[r + 8] : 0.f;
        #pragma unroll
        for (int nf = 0; nf < 4; nf++) {
            int c = n0 + wn * 32 + nf * 8 + ((lane & 3) << 1);
            #pragma unroll
            for (int u = 0; u < 2; u++) {
                int col = c + u;
                if (col < N) {
                    float bc = biasCol ? biasCol[col] : 0.f;
                    Cb[(size_t)r * N + col]       = acc[mf][nf][u]     + br0 + bc;
                    Cb[(size_t)(r + 8) * N + col] = acc[mf][nf][u + 2] + br1 + bc;
                }
            }
        }
    }
}

// ---------------- elementwise / setup kernels ----------------
__global__ void sa_init() {
    int i = blockIdx.x * 256 + threadIdx.x;
    if (i < NQ) g_flags[i] = 0;
    if (i < BQ) g_acc[i] = 0.f;
}

// generic fp32 -> bf16 hi/lo split, K-pad, optional per-col affine + leaky
__global__ void cv_split(const float* __restrict__ src, ush* __restrict__ dh, ush* __restrict__ dl,
                         long long total, int Ksrc, int Kp,
                         const float* __restrict__ sc, const float* __restrict__ sh, int leaky)
{
    long long i = (long long)blockIdx.x * 256 + threadIdx.x;
    if (i >= total) return;
    int c = (int)(i % Kp);
    long long r = i / Kp;
    float v = 0.f;
    if (c < Ksrc) {
        v = src[r * Ksrc + c];
        if (sc) { v = sc[c] * v + sh[c]; if (leaky && v < 0.f) v *= 0.2f; }
    }
    split_write(v, dh + i, dl + i);
}

// aggc (b,n,96) from channel-major inputs
__global__ void cv_agg(const float* __restrict__ points, const float* __restrict__ xyz) {
    long long i = (long long)blockIdx.x * 256 + threadIdx.x;
    if (i >= (long long)BQ*NQ*KP1) return;
    int c = (int)(i % KP1); long long r = i / KP1;
    int n = (int)(r % NQ); int b = (int)(r / NQ);
    float v = 0.f;
    if (c < DQ) v = points[((size_t)b*DQ + c)*NQ + n];
    else if (c < SCQ) v = xyz[((size_t)b*3 + (c-DQ))*NQ + n];
    split_write(v, g_aggc_h + i, g_aggc_l + i);
}

// ball query -> g_idx (b,k,n)
__global__ void sa_ball(const float* __restrict__ xyz) {
    int w = (blockIdx.x * blockDim.x + threadIdx.x) >> 5;
    int lane = threadIdx.x & 31;
    if (w >= BQ * NQ) return;
    int b = w / NQ, n = w % NQ;
    const float* X = xyz + (size_t)b * 3 * NQ;
    float px = X[n], py = X[NQ+n], pz = X[2*NQ+n];
    float pn = px*px + py*py + pz*pz;
    const float RR = (float)(0.2 * 0.2);
    int* out = g_idx + (size_t)b * NSQ * NQ + n;
    int cnt = 0;
    for (int j0 = 0; j0 < NQ && cnt < NSQ; j0 += 32) {
        int j = j0 + lane;
        float qx = X[j], qy = X[NQ+j], qz = X[2*NQ+j];
        float sq = (pn + qx*qx+qy*qy+qz*qz) - 2.0f*(px*qx+py*qy+pz*qz);
        bool in = !(sq > RR);
        unsigned m = __ballot_sync(0xffffffffu, in);
        int pos = cnt + __popc(m & ((1u << lane) - 1u));
        if (in && pos < NSQ) out[(size_t)pos * NQ] = j;
        cnt += __popc(m);
    }
    __syncwarp();
    if (lane == 0) {
        int first = out[0];
        for (int t = cnt; t < NSQ; t++) out[(size_t)t * NQ] = first;
    }
}

// BmTc (b,j,n) built directly in bf16 hi/lo; j on grid.y (uniform branches)
__global__ void sa_bmt_c(const float* __restrict__ points, const float* __restrict__ xyz) {
    int n = blockIdx.x * 256 + threadIdx.x;
    int j = blockIdx.y, b = blockIdx.z;
    float v;
    if (j < OFF_P) v = xyz[((size_t)b*3 + j)*NQ + n];
    else if (j < OFF_GP) v = points[((size_t)b*DQ + (j-OFF_P))*NQ + n];
    else if (j < OFF_GX) {
        int t = j - OFF_GP, k = t >> 6, d = t & 63;
        int ii = g_idx[((size_t)b*NSQ + k)*NQ + n];
        v = points[((size_t)b*DQ + d)*NQ + ii];
    } else {
        int t = j - OFF_GX, k = t / 3, c = t % 3;
        int ii = g_idx[((size_t)b*NSQ + k)*NQ + n];
        v = xyz[((size_t)b*3 + c)*NQ + ii];
    }
    size_t o = ((size_t)b*JQ + j)*NQ + n;
    split_write(v, g_BmTc_h + o, g_BmTc_l + o);
}

// column-channel BN stats
__global__ void sa_cs_part(const float* __restrict__ X, int C, int totalRows, int rpc) {
    int chunk = blockIdx.x, tid = threadIdx.x;
    if (tid >= C) return;
    double s = 0.0, s2 = 0.0;
    int r1 = min((chunk + 1) * rpc, totalRows);
    for (int r = chunk * rpc; r < r1; r++) {
        double v = X[(size_t)r * C + tid];
        s += v; s2 += v * v;
    }
    g_part[((size_t)chunk * C + tid) * 2] = s;
    g_part[((size_t)chunk * C + tid) * 2 + 1] = s2;
}
__global__ void sa_cs_fin(int C, int nChunks, int count,
                          const float* __restrict__ gamma, const float* __restrict__ beta,
                          float* __restrict__ sc, float* __restrict__ sf) {
    int c = blockIdx.x, tid = threadIdx.x;
    double s = 0.0, s2 = 0.0;
    for (int i = tid; i < nChunks; i += 256) {
        s  += g_part[((size_t)i * C + c) * 2];
        s2 += g_part[((size_t)i * C + c) * 2 + 1];
    }
    __shared__ double sa[256], sb2[256];
    sa[tid] = s; sb2[tid] = s2; __syncthreads();
    for (int o = 128; o > 0; o >>= 1) {
        if (tid < o) { sa[tid] += sa[tid+o]; sb2[tid] += sb2[tid+o]; }
        __syncthreads();
    }
    if (tid == 0) {
        double n = (double)count, m = sa[0] / n;
        double var = sb2[0] / n - m * m; if (var < 0.0) var = 0.0;
        float scale = gamma[c] * rsqrtf((float)var + 1e-5f);
        sc[c] = scale; sf[c] = beta[c] - (float)m * scale;
    }
}

// row-channel BN stats for h2
__global__ void sa_rstats(const float* __restrict__ X, int Cch, int L,
                          const float* __restrict__ gamma, const float* __restrict__ beta,
                          float* __restrict__ sc, float* __restrict__ sf) {
    int c = blockIdx.x, tid = threadIdx.x;
    double s = 0.0, s2 = 0.0;
    for (int b = 0; b < BQ; b++) {
        const float* p = X + ((size_t)b * Cch + c) * L;
        for (int i = tid; i < L; i += 256) { double v = p[i]; s += v; s2 += v * v; }
    }
    __shared__ double ss[256], ss2[256];
    ss[tid] = s; ss2[tid] = s2; __syncthreads();
    for (int o = 128; o > 0; o >>= 1) {
        if (tid < o) { ss[tid] += ss[tid+o]; ss2[tid] += ss2[tid+o]; }
        __syncthreads();
    }
    if (tid == 0) {
        double n = (double)BQ * L, m = ss[0] / n;
        double var = ss2[0] / n - m * m; if (var < 0.0) var = 0.0;
        float scale = gamma[c] * rsqrtf((float)var + 1e-5f);
        sc[c] = scale; sf[c] = beta[c] - (float)m * scale;
    }
}

// softmax (applies bn2 affine) in place; norms + argmax(b=0); writes Sc hi/lo too
__global__ void sa_softmax(float* __restrict__ H) {
    int s = blockIdx.x, b = blockIdx.y, tid = threadIdx.x;
    float* row = H + ((size_t)b * SQ + s) * NQ;
    __shared__ float buf[NQ];
    __shared__ float red[256], rv[256];
    __shared__ int ri[256];
    float a = g_s2[s], sh = g_sh2[s];
    float lmax = -3.4e38f;
    for (int i = tid; i < NQ; i += 256) { float y = a*row[i]+sh; buf[i] = y; lmax = fmaxf(lmax, y); }
    red[tid] = lmax; __syncthreads();
    for (int o = 128; o > 0; o >>= 1) { if (tid < o) red[tid] = fmaxf(red[tid], red[tid+o]); __syncthreads(); }
    float gmax = red[0]; __syncthreads();
    float lsum = 0.f;
    for (int i = tid; i < NQ; i += 256) { float e = expf(buf[i]-gmax); buf[i] = e; lsum += e; }
    red[tid] = lsum; __syncthreads();
    for (int o = 128; o > 0; o >>= 1) { if (tid < o) red[tid] += red[tid+o]; __syncthreads(); }
    float inv = 1.f / red[0]; __syncthreads();
    float lss = 0.f, bm = -1.f; int bi = 0;
    size_t rowoff = ((size_t)b * SQ + s) * NQ;
    for (int i = tid; i < NQ; i += 256) {
        float v = buf[i] * inv; row[i] = v; lss += v*v;
        split_write(v, g_Sc_h + rowoff + i, g_Sc_l + rowoff + i);
        if (v > bm) { bm = v; bi = i; }
    }
    red[tid] = lss; rv[tid] = bm; ri[tid] = bi; __syncthreads();
    for (int o = 128; o > 0; o >>= 1) {
        if (tid < o) {
            red[tid] += red[tid+o];
            if (rv[tid+o] > rv[tid] || (rv[tid+o] == rv[tid] && ri[tid+o] < ri[tid])) { rv[tid] = rv[tid+o]; ri[tid] = ri[tid+o]; }
        }
        __syncthreads();
    }
    if (tid == 0) {
        g_norm[b*SQ+s] = sqrtf(red[0]);
        if (b == 0) g_amax[s] = ri[0];
    }
}

__global__ void sa_flags() { int s = blockIdx.x*256 + threadIdx.x; if (s < SQ) g_flags[g_amax[s]] = 1; }

__global__ void sa_cos_epi() {
    size_t i = (size_t)blockIdx.x * 256 + threadIdx.x;
    int b = (int)(i / ((size_t)SQ*SQ)), r = (int)((i / SQ) % SQ), c = (int)(i % SQ);
    float v = 0.f;
    if (r != c) {
        float cm = g_inner[i] / (g_norm[b*SQ+r] * g_norm[b*SQ+c] + 1e-10f);
        v = cm * cm;
    }
    __shared__ float red[256];
    red[threadIdx.x] = v; __syncthreads();
    for (int o = 128; o > 0; o >>= 1) { if (threadIdx.x < o) red[threadIdx.x] += red[threadIdx.x+o]; __syncthreads(); }
    if (threadIdx.x == 0) atomicAdd(&g_acc[b], red[0]);
}

__global__ void sa_newxyz(float* __restrict__ out) {
    int i = blockIdx.x * 256 + threadIdx.x;
    if (i >= BQ*3*SQ) return;
    int s = i % SQ, c = (i/SQ) % 3, b = i/(3*SQ);
    out[i] = g_Cbig[((size_t)b*SQ + s)*JQ + OFF_X + c];
}

// ETc (b, r=k*SQ+s, ch in 0..159) directly in bf16 hi/lo
__global__ void sa_et_c() {
    int r = blockIdx.x, b = blockIdx.y, ch = threadIdx.x;
    int s = r % SQ, k = r / SQ;
    const float* Cr = g_Cbig + ((size_t)b*SQ + s)*JQ;
    float v = 0.f;
    if (ch < 64) v = Cr[OFF_P + ch];
    else if (ch < 128) { int d = ch - 64; v = Cr[OFF_GP + k*DQ + d] - Cr[OFF_P + d]; }
    else if (ch < 131) v = Cr[OFF_X + (ch - 128)];
    else if (ch < INCH) { int c3 = ch - 131; v = Cr[OFF_GX + k*3 + c3] - Cr[OFF_X + c3]; }
    size_t o = ((size_t)b*KSQ + r)*KPE + ch;
    split_write(v, g_ETc_h + o, g_ETc_l + o);
}

// max over k of leaky(bn(conv2 out))
__global__ void sa_max(float* __restrict__ out) {
    int s = blockIdx.x, b = blockIdx.y, o = threadIdx.x;
    float sc = g_sc2[o], sf = g_sf2[o];
    float m = -3.4e38f;
    const float* base = g_O2T + ((size_t)b*KSQ + s)*C2Q + o;
    #pragma unroll
    for (int k = 0; k < NSQ; k++) {
        float y = sc * base[(size_t)k*SQ*C2Q] + sf;
        y = (y >= 0.f) ? y : 0.2f * y;
        m = fmaxf(m, y);
    }
    out[XYZ_OUT + ((size_t)b*C2Q + o)*SQ + s] = m;
}

__global__ void sa_scalars(float* __restrict__ out) {
    __shared__ float sfr[256]; __shared__ int sir[256];
    int tid = threadIdx.x;
    int cnt = 0;
    for (int i = tid; i < NQ; i += 256) cnt += g_flags[i];
    float l = (tid < BQ) ? sqrtf(g_acc[tid]) : 0.f;
    sfr[tid] = l; sir[tid] = cnt; __syncthreads();
    for (int o = 128; o > 0; o >>= 1) {
        if (tid < o) { sfr[tid] += sfr[tid+o]; sir[tid] += sir[tid+o]; }
        __syncthreads();
    }
    if (tid == 0) {
        out[XYZ_OUT + NP_OUT] = sfr[0] / (float)BQ;
        out[XYZ_OUT + NP_OUT + 1] = (float)sir[0];
    }
}

// ---------------- launch ----------------
static inline float* symf(const void* sym) { void* p = nullptr; cudaGetSymbolAddress(&p, sym); return (float*)p; }
static inline ush*   symu(const void* sym) { void* p = nullptr; cudaGetSymbolAddress(&p, sym); return (ush*)p; }

extern "C" void kernel_launch(void* const* d_in, const int* in_sizes, int n_in,
                              void* d_out, int out_size)
{
    const float* xyz   = (const float*)d_in[0];
    const float* points= (const float*)d_in[1];
    const float* w1_w = (const float*)d_in[2];
    const float* w1_b = (const float*)d_in[3];
    const float* bn1g = (const float*)d_in[4];
    const float* bn1b = (const float*)d_in[5];
    const float* w2_w = (const float*)d_in[6];
    const float* w2_b = (const float*)d_in[7];
    const float* bn2g = (const float*)d_in[8];
    const float* bn2b = (const float*)d_in[9];
    const float* c0w = (const float*)d_in[10];
    const float* c0b = (const float*)d_in[11];
    const float* g0  = (const float*)d_in[12];
    const float* b0  = (const float*)d_in[13];
    const float* c1w = (const float*)d_in[14];
    const float* c1b = (const float*)d_in[15];
    const float* g1  = (const float*)d_in[16];
    const float* b1  = (const float*)d_in[17];
    const float* c2w = (const float*)d_in[18];
    const float* c2b = (const float*)d_in[19];
    const float* g2  = (const float*)d_in[20];
    const float* b2  = (const float*)d_in[21];
    float* out = (float*)d_out;

    static bool attr = false;
    if (!attr) {
        cudaFuncSetAttribute(mma_gemm, cudaFuncAttributeMaxDynamicSharedMemorySize, SMEM_BYTES);
        attr = true;
    }

    float* p_h1t = symf(g_h1t);
    float* p_h2  = symf(g_h2);
    float* p_inner = symf(g_inner);
    float* p_C   = symf(g_Cbig);
    float* p_O0  = symf(g_O0T);
    float* p_O1  = symf(g_O1T);
    float* p_O2  = symf(g_O2T);
    float* p_s1 = symf(g_s1), *p_sh1 = symf(g_sh1);
    float* p_s2 = symf(g_s2), *p_sh2 = symf(g_sh2);
    float* p_sc0 = symf(g_sc0), *p_sf0 = symf(g_sf0);
    float* p_sc1 = symf(g_sc1), *p_sf1 = symf(g_sf1);
    float* p_sc2 = symf(g_sc2), *p_sf2 = symf(g_sf2);
    ush *aggh = symu(g_aggc_h), *aggl = symu(g_aggc_l);
    ush *w1h = symu(g_w1c_h), *w1l = symu(g_w1c_l);
    ush *h1h = symu(g_h1c_h), *h1l = symu(g_h1c_l);
    ush *w2h = symu(g_w2c_h), *w2l = symu(g_w2c_l);
    ush *Sh = symu(g_Sc_h), *Sl = symu(g_Sc_l);
    ush *Bmh = symu(g_BmTc_h), *Bml = symu(g_BmTc_l);
    ush *Eh = symu(g_ETc_h), *El = symu(g_ETc_l);
    ush *w0h = symu(g_c0wc_h), *w0l = symu(g_c0wc_l);
    ush *c1h = symu(g_c1wc_h), *c1l = symu(g_c1wc_l);
    ush *c2h = symu(g_c2wc_h), *c2l = symu(g_c2wc_l);
    ush *O0h = symu(g_O0c_h), *O0l = symu(g_O0c_l);
    ush *O1h = symu(g_O1c_h), *O1l = symu(g_O1c_l);

    sa_init<<<9, 256>>>();
    cv_agg<<<(int)(((long long)BQ*NQ*KP1 + 255)/256), 256>>>(points, xyz);
    cv_split<<<(SCQ*KP1 + 255)/256, 256>>>(w1_w, w1h, w1l, (long long)SCQ*KP1, SCQ, KP1, nullptr, nullptr, 0);
    cv_split<<<(SQ*KP1 + 255)/256, 256>>>(w2_w, w2h, w2l, (long long)SQ*KP1, SCQ, KP1, nullptr, nullptr, 0);
    cv_split<<<(C0Q*KPE + 255)/256, 256>>>(c0w, w0h, w0l, (long long)C0Q*KPE, INCH, KPE, nullptr, nullptr, 0);
    cv_split<<<(C1Q*C0Q + 255)/256, 256>>>(c1w, c1h, c1l, (long long)C1Q*C0Q, C0Q, C0Q, nullptr, nullptr, 0);
    cv_split<<<(C2Q*C1Q + 255)/256, 256>>>(c2w, c2h, c2l, (long long)C2Q*C1Q, C1Q, C1Q, nullptr, nullptr, 0);
    sa_ball<<<(BQ*NQ*32)/256, 256>>>(xyz);
    sa_bmt_c<<<dim3(NQ/256, JQ, BQ), 256>>>(points, xyz);

    // h1t = aggT * w1^T + w1_b
    mma_gemm<<<dim3(1, NQ/128, BQ), 256, SMEM_BYTES>>>(aggh, aggl, w1h, w1l, p_h1t,
        NQ, SCQ, KP1, (size_t)NQ*KP1, 0, (size_t)NQ*SCQ, nullptr, w1_b);
    sa_cs_part<<<128, 128>>>(p_h1t, SCQ, BQ*NQ, BQ*NQ/128);
    sa_cs_fin<<<SCQ, 256>>>(SCQ, 128, BQ*NQ, bn1g, bn1b, p_s1, p_sh1);
    cv_split<<<(int)(((long long)BQ*NQ*KP1 + 255)/256), 256>>>(p_h1t, h1h, h1l,
        (long long)BQ*NQ*KP1, SCQ, KP1, p_s1, p_sh1, 0);

    // h2 = w2 * bn1(h1)^T + w2_b
    mma_gemm<<<dim3(NQ/128, SQ/128, BQ), 256, SMEM_BYTES>>>(w2h, w2l, h1h, h1l, p_h2,
        SQ, NQ, KP1, 0, (size_t)NQ*KP1, (size_t)SQ*NQ, w2_b, nullptr);
    sa_rstats<<<SQ, 256>>>(p_h2, SQ, NQ, bn2g, bn2b, p_s2, p_sh2);
    sa_softmax<<<dim3(SQ, BQ), 256>>>(p_h2);
    sa_flags<<<2, 256>>>();

    // inner = S S^T
    mma_gemm<<<dim3(SQ/128, SQ/128, BQ), 256, SMEM_BYTES>>>(Sh, Sl, Sh, Sl, p_inner,
        SQ, SQ, NQ, (size_t)SQ*NQ, (size_t)SQ*NQ, (size_t)SQ*SQ, nullptr, nullptr);
    sa_cos_epi<<<(int)(((size_t)BQ*SQ*SQ)/256), 256>>>();

    // Cbig = S * BmT^T
    mma_gemm<<<dim3((JQ+127)/128, SQ/128, BQ), 256, SMEM_BYTES>>>(Sh, Sl, Bmh, Bml, p_C,
        SQ, JQ, NQ, (size_t)SQ*NQ, (size_t)JQ*NQ, (size_t)SQ*JQ, nullptr, nullptr);
    sa_newxyz<<<(BQ*3*SQ + 255)/256, 256>>>(out);
    sa_et_c<<<dim3(KSQ, BQ), KPE>>>();

    // conv stack (transposed outputs)
    mma_gemm<<<dim3(1, KSQ/128, BQ), 256, SMEM_BYTES>>>(Eh, El, w0h, w0l, p_O0,
        KSQ, C0Q, KPE, (size_t)KSQ*KPE, 0, (size_t)KSQ*C0Q, nullptr, c0b);
    sa_cs_part<<<256, 128>>>(p_O0, C0Q, BQ*KSQ, BQ*KSQ/256);
    sa_cs_fin<<<C0Q, 256>>>(C0Q, 256, BQ*KSQ, g0, b0, p_sc0, p_sf0);
    cv_split<<<(int)(((long long)BQ*KSQ*C0Q + 255)/256), 256>>>(p_O0, O0h, O0l,
        (long long)BQ*KSQ*C0Q, C0Q, C0Q, p_sc0, p_sf0, 1);

    mma_gemm<<<dim3(1, KSQ/128, BQ), 256, SMEM_BYTES>>>(O0h, O0l, c1h, c1l, p_O1,
        KSQ, C1Q, C0Q, (size_t)KSQ*C0Q, 0, (size_t)KSQ*C1Q, nullptr, c1b);
    sa_cs_part<<<256, 128>>>(p_O1, C1Q, BQ*KSQ, BQ*KSQ/256);
    sa_cs_fin<<<C1Q, 256>>>(C1Q, 256, BQ*KSQ, g1, b1, p_sc1, p_sf1);
    cv_split<<<(int)(((long long)BQ*KSQ*C1Q + 255)/256), 256>>>(p_O1, O1h, O1l,
        (long long)BQ*KSQ*C1Q, C1Q, C1Q, p_sc1, p_sf1, 1);

    mma_gemm<<<dim3(C2Q/128, KSQ/128, BQ), 256, SMEM_BYTES>>>(O1h, O1l, c2h, c2l, p_O2,
        KSQ, C2Q, C1Q, (size_t)KSQ*C1Q, 0, (size_t)KSQ*C2Q, nullptr, c2b);
    sa_cs_part<<<256, 256>>>(p_O2, C2Q, BQ*KSQ, BQ*KSQ/256);
    sa_cs_fin<<<C2Q, 256>>>(C2Q, 256, BQ*KSQ, g2, b2, p_sc2, p_sf2);

    sa_max<<<dim3(SQ, BQ), 256>>>(out);
    sa_scalars<<<1, 256>>>(out);
}